// round 1
// baseline (speedup 1.0000x reference)
#include <cuda_runtime.h>
#include <cuda_bf16.h>
#include <math.h>

#define LL    8192
#define DIM   256
#define DI    512
#define DCONV 4
#define NS    16
#define DTR   16
#define NE    4
#define INNER 512
#define HOR   32
#define NBLK  8
#define EPSV  1e-3f

#define NCH 128   // scan chunks
#define CL  64    // chunk length (NCH*CL == LL)

// ---------------- scratch (static device allocations only) ----------------
__device__ float g_h   [LL*DIM];
__device__ float g_hn  [LL*DIM];
__device__ float g_xT  [LL*DIM];
__device__ float g_xr  [LL*2*DI];
__device__ float g_xc  [LL*DI];
__device__ float g_xdbl[LL*(DTR+2*NS)];
__device__ float g_delta[LL*DI];     // reused as MoE g*u buffer
__device__ float g_y   [LL*DI];
__device__ float g_moe [LL*DIM];
__device__ float g_w   [LL*NE];
__device__ float g_cs  [NCH*DI*NS];
__device__ float g_sd  [NCH*DI];
__device__ float g_init[NCH*DI*NS];

__device__ __forceinline__ float siluf(float x) { return x / (1.f + expf(-x)); }

// ---------------- transpose x (DIM,L) -> xT (L,DIM) ----------------
__global__ void transpose_kernel(const float* __restrict__ x, float* __restrict__ xT)
{
    __shared__ float tile[32][33];
    int bx = blockIdx.x * 32;   // along L
    int by = blockIdx.y * 32;   // along DIM
    int tx = threadIdx.x, ty = threadIdx.y; // 32 x 8
    #pragma unroll
    for (int i = 0; i < 32; i += 8)
        tile[ty + i][tx] = x[(by + ty + i) * LL + bx + tx];
    __syncthreads();
    #pragma unroll
    for (int i = 0; i < 32; i += 8)
        xT[(bx + ty + i) * DIM + by + tx] = tile[tx][ty + i];
}

// ---------------- GEMM: C[M,N] = epilogue(A[M,K] @ W[N,K]^T) ----------------
// modes: 0 store, 1 silu, 2 add residual R, 3 C *= acc, 4 C += rs[m*rsStride]*acc
#define BM 128
#define BN 64
#define BK 16
__global__ __launch_bounds__(256)
void gemm_nt(const float* __restrict__ A, const float* __restrict__ W,
             float* __restrict__ C, const float* __restrict__ R,
             const float* __restrict__ rs, int rsStride,
             int M, int N, int K, int mode)
{
    __shared__ float As[BK][BM];
    __shared__ float Ws[BK][BN];
    int bm = blockIdx.y * BM;
    int bn = blockIdx.x * BN;
    int tid = threadIdx.x;
    int tx = tid & 15;   // n dir: 16*4 = 64
    int ty = tid >> 4;   // m dir: 16*8 = 128
    float acc[8][4];
    #pragma unroll
    for (int i = 0; i < 8; i++)
        #pragma unroll
        for (int j = 0; j < 4; j++) acc[i][j] = 0.f;

    for (int k0 = 0; k0 < K; k0 += BK) {
        #pragma unroll
        for (int q = 0; q < 8; q++) {                  // A tile: 128x16
            int idx = q * 256 + tid;
            int r = idx >> 4, c = idx & 15;
            As[c][r] = A[(size_t)(bm + r) * K + k0 + c];
        }
        #pragma unroll
        for (int q = 0; q < 4; q++) {                  // W tile: 64x16
            int idx = q * 256 + tid;
            int r = idx >> 4, c = idx & 15;
            int rn = bn + r;
            Ws[c][r] = (rn < N) ? W[(size_t)rn * K + k0 + c] : 0.f;
        }
        __syncthreads();
        #pragma unroll
        for (int k = 0; k < BK; k++) {
            float a[8], b[4];
            #pragma unroll
            for (int i = 0; i < 8; i++) a[i] = As[k][ty * 8 + i];
            #pragma unroll
            for (int j = 0; j < 4; j++) b[j] = Ws[k][tx * 4 + j];
            #pragma unroll
            for (int i = 0; i < 8; i++)
                #pragma unroll
                for (int j = 0; j < 4; j++)
                    acc[i][j] += a[i] * b[j];
        }
        __syncthreads();
    }

    #pragma unroll
    for (int i = 0; i < 8; i++) {
        int m = bm + ty * 8 + i;
        #pragma unroll
        for (int j = 0; j < 4; j++) {
            int n = bn + tx * 4 + j;
            if (n < N) {
                size_t o = (size_t)m * N + n;
                float v = acc[i][j];
                if (mode == 0)      C[o] = v;
                else if (mode == 1) C[o] = v / (1.f + expf(-v));
                else if (mode == 2) C[o] = v + R[o];
                else if (mode == 3) C[o] = C[o] * v;
                else                C[o] += rs[m * rsStride] * v;
            }
        }
    }
}

// ---------------- rmsnorm over rows of 256 (optional residual add) ----------------
__global__ void rmsnorm_kernel(const float* __restrict__ in, const float* __restrict__ w,
                               const float* __restrict__ addres, float* __restrict__ out)
{
    int l = blockIdx.x;
    int t = threadIdx.x; // 256
    float v = in[l * DIM + t];
    __shared__ float red[8];
    float s = v * v;
    #pragma unroll
    for (int o = 16; o > 0; o >>= 1) s += __shfl_xor_sync(0xffffffffu, s, o);
    if ((t & 31) == 0) red[t >> 5] = s;
    __syncthreads();
    if (t < 8) {
        float x2 = red[t];
        #pragma unroll
        for (int o = 4; o > 0; o >>= 1) x2 += __shfl_xor_sync(0xffu, x2, o);
        if (t == 0) red[0] = x2;
    }
    __syncthreads();
    float rms = rsqrtf(red[0] / (float)DIM + EPSV);
    float r = w[t] * v * rms;
    if (addres) r += addres[l * DIM + t];
    out[l * DIM + t] = r;
}

// ---------------- causal depthwise conv(4) + bias + silu ----------------
__global__ void conv_kernel(const float* __restrict__ xr, const float* __restrict__ cw,
                            const float* __restrict__ cb, float* __restrict__ xc)
{
    int idx = blockIdx.x * blockDim.x + threadIdx.x;
    if (idx >= LL * DI) return;
    int c = idx % DI, l = idx / DI;
    float w0 = cw[c * 4 + 0], w1 = cw[c * 4 + 1], w2 = cw[c * 4 + 2], w3 = cw[c * 4 + 3];
    float acc = cb[c];
    if (l >= 3) acc += xr[(size_t)(l - 3) * (2 * DI) + c] * w0;
    if (l >= 2) acc += xr[(size_t)(l - 2) * (2 * DI) + c] * w1;
    if (l >= 1) acc += xr[(size_t)(l - 1) * (2 * DI) + c] * w2;
    acc += xr[(size_t)l * (2 * DI) + c] * w3;
    xc[idx] = siluf(acc);
}

// ---------------- delta = softplus(dr @ dtw^T + dtb) ----------------
__global__ void delta_kernel(const float* __restrict__ xdbl, const float* __restrict__ dtw,
                             const float* __restrict__ dtb, float* __restrict__ delta)
{
    int l = blockIdx.x;
    __shared__ float dr[DTR];
    if (threadIdx.x < DTR) dr[threadIdx.x] = xdbl[l * 48 + threadIdx.x];
    __syncthreads();
    for (int d = threadIdx.x; d < DI; d += blockDim.x) {
        float acc = dtb[d];
        #pragma unroll
        for (int r = 0; r < DTR; r++) acc += dr[r] * dtw[d * DTR + r];
        float sp = (acc > 20.f) ? acc : log1pf(expf(acc));
        delta[(size_t)l * DI + d] = sp;
    }
}

// ---------------- gate: scores, top-2 softmax weights ----------------
__global__ void gate_kernel(const float* __restrict__ h, const float* __restrict__ gw,
                            float* __restrict__ wout)
{
    __shared__ float sgw[NE * DIM];
    int tid = threadIdx.x; // 256
    for (int i = tid; i < NE * DIM; i += 256) sgw[i] = gw[i];
    __syncthreads();
    int warp = tid >> 5, lane = tid & 31;
    int t = blockIdx.x * 8 + warp;
    float acc[NE] = {0.f, 0.f, 0.f, 0.f};
    for (int k = lane; k < DIM; k += 32) {
        float hv = h[(size_t)t * DIM + k];
        #pragma unroll
        for (int e = 0; e < NE; e++) acc[e] += hv * sgw[e * DIM + k];
    }
    #pragma unroll
    for (int e = 0; e < NE; e++)
        #pragma unroll
        for (int o = 16; o > 0; o >>= 1) acc[e] += __shfl_xor_sync(0xffffffffu, acc[e], o);
    if (lane == 0) {
        int i1 = 0; float v1 = acc[0];
        for (int e = 1; e < NE; e++) if (acc[e] > v1) { v1 = acc[e]; i1 = e; }
        int i2 = -1; float v2 = -1e30f;
        for (int e = 0; e < NE; e++) if (e != i1 && acc[e] > v2) { v2 = acc[e]; i2 = e; }
        float ew = expf(v2 - v1);
        float w1 = 1.f / (1.f + ew), w2 = ew / (1.f + ew);
        float w[NE] = {0.f, 0.f, 0.f, 0.f};
        w[i1] = w1; w[i2] = w2;
        #pragma unroll
        for (int e = 0; e < NE; e++) wout[t * NE + e] = w[e];
    }
}

// ---------------- chunked selective scan ----------------
// phase 1: per-chunk local scan (zero init) + sum(delta) per (chunk,d)
__global__ void scan_p1(const float* __restrict__ delta, const float* __restrict__ xc,
                        const float* __restrict__ xdbl, const float* __restrict__ Alog,
                        float* __restrict__ cs, float* __restrict__ sd)
{
    int b = blockIdx.x;          // NCH * (DI/8)
    int chunk = b >> 6;          // DI/8 = 64
    int dg = b & 63;
    int tid = threadIdx.x;       // 128 = 8 d x 16 n
    int dl = tid >> 4, n = tid & 15;
    int d = dg * 8 + dl;
    float Acoef = -expf(Alog[d * NS + n]);
    float s = 0.f, sdl = 0.f;
    int l0 = chunk * CL;
    for (int i = 0; i < CL; i++) {
        int l = l0 + i;
        float dt = delta[(size_t)l * DI + d];
        float x  = xc[(size_t)l * DI + d];
        float Bv = xdbl[l * 48 + DTR + n];
        s = expf(dt * Acoef) * s + dt * Bv * x;
        sdl += dt;
    }
    cs[((size_t)chunk * DI + d) * NS + n] = s;
    if (n == 0) sd[chunk * DI + d] = sdl;
}

// phase 2: sequential prefix over chunks, store init state per chunk
__global__ void scan_p2(const float* __restrict__ Alog, const float* __restrict__ cs,
                        const float* __restrict__ sd, float* __restrict__ init)
{
    int idx = blockIdx.x * blockDim.x + threadIdx.x; // DI*NS = 8192
    int d = idx >> 4, n = idx & 15;
    float Acoef = -expf(Alog[d * NS + n]);
    float S = 0.f;
    for (int c = 0; c < NCH; c++) {
        init[((size_t)c * DI + d) * NS + n] = S;
        S = expf(Acoef * sd[c * DI + d]) * S + cs[((size_t)c * DI + d) * NS + n];
    }
}

// phase 3: rescan with correct init, project with C, +xc*D, *silu(res)
__global__ void scan_p3(const float* __restrict__ delta, const float* __restrict__ xc,
                        const float* __restrict__ xdbl, const float* __restrict__ Alog,
                        const float* __restrict__ init, const float* __restrict__ Dp,
                        const float* __restrict__ xr, float* __restrict__ y)
{
    int b = blockIdx.x;
    int chunk = b >> 6;
    int dg = b & 63;
    int tid = threadIdx.x;
    int dl = tid >> 4, n = tid & 15;
    int d = dg * 8 + dl;
    float Acoef = -expf(Alog[d * NS + n]);
    float s = init[((size_t)chunk * DI + d) * NS + n];
    float Dv = Dp[d];
    int l0 = chunk * CL;
    for (int i = 0; i < CL; i++) {
        int l = l0 + i;
        float dt = delta[(size_t)l * DI + d];
        float x  = xc[(size_t)l * DI + d];
        float Bv = xdbl[l * 48 + DTR + n];
        float Cv = xdbl[l * 48 + DTR + NS + n];
        s = expf(dt * Acoef) * s + dt * Bv * x;
        float part = s * Cv;
        #pragma unroll
        for (int o = 1; o < 16; o <<= 1)
            part += __shfl_xor_sync(0xffffffffu, part, o, 16);
        if (n == 0) {
            float res = xr[(size_t)l * (2 * DI) + DI + d];
            y[(size_t)l * DI + d] = (part + x * Dv) * siluf(res);
        }
    }
}

// ---------------- head2: out[o,l] = sigmoid(a[l,:] . w2[o,:]) ----------------
__global__ void head2_kernel(const float* __restrict__ a, const float* __restrict__ w2,
                             float* __restrict__ out)
{
    int idx = blockIdx.x * blockDim.x + threadIdx.x; // LL*HOR
    int o = idx & 31, l = idx >> 5;
    const float* ar = a + (size_t)l * DIM;
    const float* wr = w2 + (size_t)o * DIM;
    float acc = 0.f;
    #pragma unroll 8
    for (int k = 0; k < DIM; k++) acc += ar[k] * wr[k];
    out[(size_t)o * LL + l] = 1.f / (1.f + expf(-acc));
}

// ---------------- host orchestration ----------------
extern "C" void kernel_launch(void* const* d_in, const int* in_sizes, int n_in,
                              void* d_out, int out_size)
{
    const float* x         = (const float*)d_in[0];
    const float* lin_w     = (const float*)d_in[1];
    const float* in_proj_w = (const float*)d_in[2];
    const float* conv_w    = (const float*)d_in[3];
    const float* conv_b    = (const float*)d_in[4];
    const float* x_proj_w  = (const float*)d_in[5];
    const float* dt_proj_w = (const float*)d_in[6];
    const float* dt_proj_b = (const float*)d_in[7];
    const float* A_log     = (const float*)d_in[8];
    const float* D_param   = (const float*)d_in[9];
    const float* out_proj_w= (const float*)d_in[10];
    const float* gate_w    = (const float*)d_in[11];
    const float* gproj_w   = (const float*)d_in[12];
    const float* uproj_w   = (const float*)d_in[13];
    const float* dproj_w   = (const float*)d_in[14];
    const float* rms_a_w   = (const float*)d_in[15];
    const float* rms_f_w   = (const float*)d_in[16];
    const float* head_w1   = (const float*)d_in[17];
    const float* head_w2   = (const float*)d_in[18];
    float* out = (float*)d_out;

    float *h, *hn, *xT, *xr, *xc, *xdbl, *delta, *y, *moe, *w, *cs, *sd, *init;
    cudaGetSymbolAddress((void**)&h,    g_h);
    cudaGetSymbolAddress((void**)&hn,   g_hn);
    cudaGetSymbolAddress((void**)&xT,   g_xT);
    cudaGetSymbolAddress((void**)&xr,   g_xr);
    cudaGetSymbolAddress((void**)&xc,   g_xc);
    cudaGetSymbolAddress((void**)&xdbl, g_xdbl);
    cudaGetSymbolAddress((void**)&delta,g_delta);
    cudaGetSymbolAddress((void**)&y,    g_y);
    cudaGetSymbolAddress((void**)&moe,  g_moe);
    cudaGetSymbolAddress((void**)&w,    g_w);
    cudaGetSymbolAddress((void**)&cs,   g_cs);
    cudaGetSymbolAddress((void**)&sd,   g_sd);
    cudaGetSymbolAddress((void**)&init, g_init);
    float* gu = delta; // reuse

    auto gemm = [&](const float* A, const float* W, float* C, const float* R,
                    const float* rs, int rsStride, int N, int K, int mode) {
        dim3 grid((N + BN - 1) / BN, LL / BM);
        gemm_nt<<<grid, 256>>>(A, W, C, R, rs, rsStride, LL, N, K, mode);
    };

    // h = x.T @ lin_w.T
    transpose_kernel<<<dim3(LL / 32, DIM / 32), dim3(32, 8)>>>(x, xT);
    gemm(xT, lin_w, h, nullptr, nullptr, 0, DIM, DIM, 0);

    for (int i = 0; i < NBLK; i++) {
        // ---- mamba ----
        rmsnorm_kernel<<<LL, DIM>>>(h, rms_a_w, nullptr, hn);
        gemm(hn, in_proj_w + (size_t)i * 2 * DI * DIM, xr, nullptr, nullptr, 0, 2 * DI, DIM, 0);
        conv_kernel<<<(LL * DI + 255) / 256, 256>>>(xr, conv_w + (size_t)i * DI * DCONV,
                                                    conv_b + (size_t)i * DI, xc);
        gemm(xc, x_proj_w + (size_t)i * 48 * DI, xdbl, nullptr, nullptr, 0, 48, DI, 0);
        delta_kernel<<<LL, 256>>>(xdbl, dt_proj_w + (size_t)i * DI * DTR,
                                  dt_proj_b + (size_t)i * DI, delta);
        const float* Alog_i = A_log + (size_t)i * DI * NS;
        scan_p1<<<NCH * (DI / 8), 128>>>(delta, xc, xdbl, Alog_i, cs, sd);
        scan_p2<<<DI * NS / 256, 256>>>(Alog_i, cs, sd, init);
        scan_p3<<<NCH * (DI / 8), 128>>>(delta, xc, xdbl, Alog_i, init,
                                         D_param + (size_t)i * DI, xr, y);
        // h = out_proj(y) + h (residual)
        gemm(y, out_proj_w + (size_t)i * DIM * DI, h, h, nullptr, 0, DIM, DI, 2);

        // ---- MoE ----
        gate_kernel<<<LL / 8, 256>>>(h, gate_w + (size_t)i * NE * DIM, w);
        cudaMemsetAsync(moe, 0, (size_t)LL * DIM * sizeof(float));
        for (int e = 0; e < NE; e++) {
            const float* gp = gproj_w + ((size_t)i * NE + e) * INNER * DIM;
            const float* up = uproj_w + ((size_t)i * NE + e) * INNER * DIM;
            const float* dp = dproj_w + ((size_t)i * NE + e) * DIM * INNER;
            gemm(h, gp, gu, nullptr, nullptr, 0, INNER, DIM, 1);   // gu = silu(h@gp^T)
            gemm(h, up, gu, nullptr, nullptr, 0, INNER, DIM, 3);   // gu *= h@up^T
            gemm(gu, dp, moe, nullptr, w + e, NE, DIM, INNER, 4);  // moe += w[t,e]*(gu@dp^T)
        }
        // h = rmsnorm(moe) + h
        rmsnorm_kernel<<<LL, DIM>>>(moe, rms_f_w, h, h);
    }

    // head
    gemm(h, lin_w, hn, nullptr, nullptr, 0, DIM, DIM, 0);
    gemm(hn, head_w1, xT, nullptr, nullptr, 0, DIM, DIM, 1);
    head2_kernel<<<LL * HOR / 256, 256>>>(xT, head_w2, out);
}

// round 3
// speedup vs baseline: 2.2921x; 2.2921x over previous
#include <cuda_runtime.h>
#include <cuda_bf16.h>
#include <math.h>
#include <stdint.h>

#define LL    8192
#define DIM   256
#define DI    512
#define DCONV 4
#define NS    16
#define DTR   16
#define NE    4
#define INNER 512
#define HOR   32
#define NBLK  8
#define EPSV  1e-3f

#define NCH 128   // scan chunks
#define CL  64    // chunk length (NCH*CL == LL)

// ---------------- scratch (static device allocations only) ----------------
__device__ float g_h   [LL*DIM];
__device__ float g_hn  [LL*DIM];
__device__ float g_xT  [LL*DIM];
__device__ float g_xr  [LL*2*DI];
__device__ float g_xc  [LL*DI];
__device__ float g_xdbl[LL*(DTR+2*NS)];
__device__ float g_delta[LL*DI];     // reused as MoE g*u buffer
__device__ float g_y   [LL*DI];
__device__ float g_moe [LL*DIM];
__device__ float g_w   [LL*NE];
__device__ float g_cs  [NCH*DI*NS];
__device__ float g_sd  [NCH*DI];
__device__ float g_init[NCH*DI*NS];

__device__ __forceinline__ float siluf(float x) { return x / (1.f + expf(-x)); }

__device__ __forceinline__ unsigned int f2tf32(float f) {
    unsigned int r;
    asm("cvt.rna.tf32.f32 %0, %1;" : "=r"(r) : "f"(f));
    return r;
}

__device__ __forceinline__ void mma_tf32(float c[4], const unsigned int a[4], const unsigned int b[2]) {
    asm volatile("mma.sync.aligned.m16n8k8.row.col.f32.tf32.tf32.f32 "
        "{%0,%1,%2,%3}, {%4,%5,%6,%7}, {%8,%9}, {%0,%1,%2,%3};"
        : "+f"(c[0]), "+f"(c[1]), "+f"(c[2]), "+f"(c[3])
        : "r"(a[0]), "r"(a[1]), "r"(a[2]), "r"(a[3]), "r"(b[0]), "r"(b[1]));
}

// ---------------- transpose x (DIM,L) -> xT (L,DIM) ----------------
__global__ void transpose_kernel(const float* __restrict__ x, float* __restrict__ xT)
{
    __shared__ float tile[32][33];
    int bx = blockIdx.x * 32;   // along L
    int by = blockIdx.y * 32;   // along DIM
    int tx = threadIdx.x, ty = threadIdx.y; // 32 x 8
    #pragma unroll
    for (int i = 0; i < 32; i += 8)
        tile[ty + i][tx] = x[(by + ty + i) * LL + bx + tx];
    __syncthreads();
    #pragma unroll
    for (int i = 0; i < 32; i += 8)
        xT[(bx + ty + i) * DIM + by + tx] = tile[tx][ty + i];
}

// ---------------- tensor-core GEMM: C[M,N] = epi(A[M,K] @ W[N,K]^T) ----------------
// modes: 0 store, 1 silu, 2 add residual R, 3 C *= acc, 4 C += rs[m*rsStride]*acc
// Tiles: 128x64x32, 8 warps (4m x 2n), warp tile 32x32 = 2x4 m16n8k8 mmas.
// smem rows padded to 36 u32: frag LDS bank = (4*row + col) % 32 -> conflict-free.
#define BM 128
#define BN 64
#define BK 32
#define SST 36

__global__ __launch_bounds__(256)
void gemm_tc(const float* __restrict__ A, const float* __restrict__ W,
             float* __restrict__ C, const float* __restrict__ R,
             const float* __restrict__ rs, int rsStride,
             int M, int N, int K, int mode)
{
    __shared__ unsigned int As[BM * SST];
    __shared__ unsigned int Bs[BN * SST];
    int bm = blockIdx.y * BM;
    int bn = blockIdx.x * BN;
    int tid = threadIdx.x;
    int lane = tid & 31;
    int warp = tid >> 5;
    int wm = (warp & 3) * 32;   // warp m offset
    int wn = (warp >> 2) * 32;  // warp n offset

    float acc[2][4][4];
    #pragma unroll
    for (int mt = 0; mt < 2; mt++)
        #pragma unroll
        for (int nt = 0; nt < 4; nt++)
            #pragma unroll
            for (int q = 0; q < 4; q++) acc[mt][nt][q] = 0.f;

    float4 pa[4], pb[2];

    // gmem -> regs
    auto loadA = [&](int k0) {
        #pragma unroll
        for (int q = 0; q < 4; q++) {
            int fi = q * 256 + tid;
            int r = fi >> 3, c4 = fi & 7;
            pa[q] = *(const float4*)&A[(size_t)(bm + r) * K + k0 + c4 * 4];
        }
    };
    auto loadB = [&](int k0) {
        #pragma unroll
        for (int q = 0; q < 2; q++) {
            int fi = q * 256 + tid;
            int r = fi >> 3, c4 = fi & 7;
            if (bn + r < N)
                pb[q] = *(const float4*)&W[(size_t)(bn + r) * K + k0 + c4 * 4];
            else
                pb[q] = make_float4(0.f, 0.f, 0.f, 0.f);
        }
    };
    // regs -> smem (tf32 convert)
    auto storeAB = [&]() {
        #pragma unroll
        for (int q = 0; q < 4; q++) {
            int fi = q * 256 + tid;
            int r = fi >> 3, c4 = fi & 7;
            uint4 v = make_uint4(f2tf32(pa[q].x), f2tf32(pa[q].y), f2tf32(pa[q].z), f2tf32(pa[q].w));
            *(uint4*)&As[r * SST + c4 * 4] = v;
        }
        #pragma unroll
        for (int q = 0; q < 2; q++) {
            int fi = q * 256 + tid;
            int r = fi >> 3, c4 = fi & 7;
            uint4 v = make_uint4(f2tf32(pb[q].x), f2tf32(pb[q].y), f2tf32(pb[q].z), f2tf32(pb[q].w));
            *(uint4*)&Bs[r * SST + c4 * 4] = v;
        }
    };

    loadA(0); loadB(0);
    storeAB();
    __syncthreads();

    int rq = lane >> 2;
    int cq = lane & 3;

    for (int k0 = 0;;) {
        int nxt = k0 + BK;
        if (nxt < K) { loadA(nxt); loadB(nxt); }

        #pragma unroll
        for (int kk = 0; kk < 4; kk++) {
            int kb = kk * 8 + cq;
            unsigned int a[2][4], b[4][2];
            #pragma unroll
            for (int mt = 0; mt < 2; mt++) {
                int rb = wm + mt * 16 + rq;
                a[mt][0] = As[rb * SST + kb];
                a[mt][1] = As[(rb + 8) * SST + kb];
                a[mt][2] = As[rb * SST + kb + 4];
                a[mt][3] = As[(rb + 8) * SST + kb + 4];
            }
            #pragma unroll
            for (int nt = 0; nt < 4; nt++) {
                int cb = wn + nt * 8 + rq;
                b[nt][0] = Bs[cb * SST + kb];
                b[nt][1] = Bs[cb * SST + kb + 4];
            }
            #pragma unroll
            for (int mt = 0; mt < 2; mt++)
                #pragma unroll
                for (int nt = 0; nt < 4; nt++)
                    mma_tf32(acc[mt][nt], a[mt], b[nt]);
        }

        k0 = nxt;
        if (k0 >= K) break;
        __syncthreads();
        storeAB();
        __syncthreads();
    }

    // epilogue
    int cc = cq * 2;
    #pragma unroll
    for (int mt = 0; mt < 2; mt++) {
        #pragma unroll
        for (int half = 0; half < 2; half++) {
            int m = bm + wm + mt * 16 + rq + half * 8;
            float rsv = (mode == 4) ? rs[m * rsStride] : 0.f;
            #pragma unroll
            for (int nt = 0; nt < 4; nt++) {
                int n = bn + wn + nt * 8 + cc;
                if (n < N) {
                    size_t o = (size_t)m * N + n;
                    float v0 = acc[mt][nt][half * 2 + 0];
                    float v1 = acc[mt][nt][half * 2 + 1];
                    if (mode == 0) {
                        C[o] = v0; C[o + 1] = v1;
                    } else if (mode == 1) {
                        C[o]     = v0 / (1.f + expf(-v0));
                        C[o + 1] = v1 / (1.f + expf(-v1));
                    } else if (mode == 2) {
                        C[o] = v0 + R[o]; C[o + 1] = v1 + R[o + 1];
                    } else if (mode == 3) {
                        C[o] *= v0; C[o + 1] *= v1;
                    } else {
                        C[o] += rsv * v0; C[o + 1] += rsv * v1;
                    }
                }
            }
        }
    }
}

// ---------------- rmsnorm over rows of 256 (optional residual add) ----------------
__global__ void rmsnorm_kernel(const float* __restrict__ in, const float* __restrict__ w,
                               const float* __restrict__ addres, float* __restrict__ out)
{
    int l = blockIdx.x;
    int t = threadIdx.x; // 256
    float v = in[l * DIM + t];
    __shared__ float red[8];
    float s = v * v;
    #pragma unroll
    for (int o = 16; o > 0; o >>= 1) s += __shfl_xor_sync(0xffffffffu, s, o);
    if ((t & 31) == 0) red[t >> 5] = s;
    __syncthreads();
    if (t < 8) {
        float x2 = red[t];
        #pragma unroll
        for (int o = 4; o > 0; o >>= 1) x2 += __shfl_xor_sync(0xffu, x2, o);
        if (t == 0) red[0] = x2;
    }
    __syncthreads();
    float rms = rsqrtf(red[0] / (float)DIM + EPSV);
    float r = w[t] * v * rms;
    if (addres) r += addres[l * DIM + t];
    out[l * DIM + t] = r;
}

// ---------------- causal depthwise conv(4) + bias + silu ----------------
__global__ void conv_kernel(const float* __restrict__ xr, const float* __restrict__ cw,
                            const float* __restrict__ cb, float* __restrict__ xc)
{
    int idx = blockIdx.x * blockDim.x + threadIdx.x;
    if (idx >= LL * DI) return;
    int c = idx % DI, l = idx / DI;
    float w0 = cw[c * 4 + 0], w1 = cw[c * 4 + 1], w2 = cw[c * 4 + 2], w3 = cw[c * 4 + 3];
    float acc = cb[c];
    if (l >= 3) acc += xr[(size_t)(l - 3) * (2 * DI) + c] * w0;
    if (l >= 2) acc += xr[(size_t)(l - 2) * (2 * DI) + c] * w1;
    if (l >= 1) acc += xr[(size_t)(l - 1) * (2 * DI) + c] * w2;
    acc += xr[(size_t)l * (2 * DI) + c] * w3;
    xc[idx] = siluf(acc);
}

// ---------------- delta = softplus(dr @ dtw^T + dtb) ----------------
__global__ void delta_kernel(const float* __restrict__ xdbl, const float* __restrict__ dtw,
                             const float* __restrict__ dtb, float* __restrict__ delta)
{
    int l = blockIdx.x;
    __shared__ float dr[DTR];
    if (threadIdx.x < DTR) dr[threadIdx.x] = xdbl[l * 48 + threadIdx.x];
    __syncthreads();
    for (int d = threadIdx.x; d < DI; d += blockDim.x) {
        float acc = dtb[d];
        #pragma unroll
        for (int r = 0; r < DTR; r++) acc += dr[r] * dtw[d * DTR + r];
        float sp = (acc > 20.f) ? acc : log1pf(expf(acc));
        delta[(size_t)l * DI + d] = sp;
    }
}

// ---------------- gate: scores, top-2 softmax weights ----------------
__global__ void gate_kernel(const float* __restrict__ h, const float* __restrict__ gw,
                            float* __restrict__ wout)
{
    __shared__ float sgw[NE * DIM];
    int tid = threadIdx.x; // 256
    for (int i = tid; i < NE * DIM; i += 256) sgw[i] = gw[i];
    __syncthreads();
    int warp = tid >> 5, lane = tid & 31;
    int t = blockIdx.x * 8 + warp;
    float acc[NE] = {0.f, 0.f, 0.f, 0.f};
    for (int k = lane; k < DIM; k += 32) {
        float hv = h[(size_t)t * DIM + k];
        #pragma unroll
        for (int e = 0; e < NE; e++) acc[e] += hv * sgw[e * DIM + k];
    }
    #pragma unroll
    for (int e = 0; e < NE; e++)
        #pragma unroll
        for (int o = 16; o > 0; o >>= 1) acc[e] += __shfl_xor_sync(0xffffffffu, acc[e], o);
    if (lane == 0) {
        int i1 = 0; float v1 = acc[0];
        for (int e = 1; e < NE; e++) if (acc[e] > v1) { v1 = acc[e]; i1 = e; }
        int i2 = -1; float v2 = -1e30f;
        for (int e = 0; e < NE; e++) if (e != i1 && acc[e] > v2) { v2 = acc[e]; i2 = e; }
        float ew = expf(v2 - v1);
        float w1 = 1.f / (1.f + ew), w2 = ew / (1.f + ew);
        float w[NE] = {0.f, 0.f, 0.f, 0.f};
        w[i1] = w1; w[i2] = w2;
        #pragma unroll
        for (int e = 0; e < NE; e++) wout[t * NE + e] = w[e];
    }
}

// ---------------- chunked selective scan ----------------
__global__ void scan_p1(const float* __restrict__ delta, const float* __restrict__ xc,
                        const float* __restrict__ xdbl, const float* __restrict__ Alog,
                        float* __restrict__ cs, float* __restrict__ sd)
{
    int b = blockIdx.x;          // NCH * (DI/8)
    int chunk = b >> 6;
    int dg = b & 63;
    int tid = threadIdx.x;       // 128 = 8 d x 16 n
    int dl = tid >> 4, n = tid & 15;
    int d = dg * 8 + dl;
    float Acoef = -__expf(Alog[d * NS + n]);
    float s = 0.f, sdl = 0.f;
    int l0 = chunk * CL;
    for (int i = 0; i < CL; i++) {
        int l = l0 + i;
        float dt = delta[(size_t)l * DI + d];
        float x  = xc[(size_t)l * DI + d];
        float Bv = xdbl[l * 48 + DTR + n];
        s = __expf(dt * Acoef) * s + dt * Bv * x;
        sdl += dt;
    }
    cs[((size_t)chunk * DI + d) * NS + n] = s;
    if (n == 0) sd[chunk * DI + d] = sdl;
}

__global__ void scan_p2(const float* __restrict__ Alog, const float* __restrict__ cs,
                        const float* __restrict__ sd, float* __restrict__ init)
{
    int idx = blockIdx.x * blockDim.x + threadIdx.x; // DI*NS = 8192
    int d = idx >> 4, n = idx & 15;
    float Acoef = -__expf(Alog[d * NS + n]);
    float S = 0.f;
    for (int c = 0; c < NCH; c++) {
        init[((size_t)c * DI + d) * NS + n] = S;
        S = __expf(Acoef * sd[c * DI + d]) * S + cs[((size_t)c * DI + d) * NS + n];
    }
}

__global__ void scan_p3(const float* __restrict__ delta, const float* __restrict__ xc,
                        const float* __restrict__ xdbl, const float* __restrict__ Alog,
                        const float* __restrict__ init, const float* __restrict__ Dp,
                        const float* __restrict__ xr, float* __restrict__ y)
{
    int b = blockIdx.x;
    int chunk = b >> 6;
    int dg = b & 63;
    int tid = threadIdx.x;
    int dl = tid >> 4, n = tid & 15;
    int d = dg * 8 + dl;
    float Acoef = -__expf(Alog[d * NS + n]);
    float s = init[((size_t)chunk * DI + d) * NS + n];
    float Dv = Dp[d];
    int l0 = chunk * CL;
    for (int i = 0; i < CL; i++) {
        int l = l0 + i;
        float dt = delta[(size_t)l * DI + d];
        float x  = xc[(size_t)l * DI + d];
        float Bv = xdbl[l * 48 + DTR + n];
        float Cv = xdbl[l * 48 + DTR + NS + n];
        s = __expf(dt * Acoef) * s + dt * Bv * x;
        float part = s * Cv;
        #pragma unroll
        for (int o = 1; o < 16; o <<= 1)
            part += __shfl_xor_sync(0xffffffffu, part, o, 16);
        if (n == 0) {
            float res = xr[(size_t)l * (2 * DI) + DI + d];
            y[(size_t)l * DI + d] = (part + x * Dv) * siluf(res);
        }
    }
}

// ---------------- head2: out[o,l] = sigmoid(a[l,:] . w2[o,:]) ----------------
__global__ void head2_kernel(const float* __restrict__ a, const float* __restrict__ w2,
                             float* __restrict__ out)
{
    int idx = blockIdx.x * blockDim.x + threadIdx.x; // LL*HOR
    int o = idx & 31, l = idx >> 5;
    const float* ar = a + (size_t)l * DIM;
    const float* wr = w2 + (size_t)o * DIM;
    float acc = 0.f;
    #pragma unroll 8
    for (int k = 0; k < DIM; k++) acc += ar[k] * wr[k];
    out[(size_t)o * LL + l] = 1.f / (1.f + expf(-acc));
}

// ---------------- host orchestration ----------------
extern "C" void kernel_launch(void* const* d_in, const int* in_sizes, int n_in,
                              void* d_out, int out_size)
{
    const float* x         = (const float*)d_in[0];
    const float* lin_w     = (const float*)d_in[1];
    const float* in_proj_w = (const float*)d_in[2];
    const float* conv_w    = (const float*)d_in[3];
    const float* conv_b    = (const float*)d_in[4];
    const float* x_proj_w  = (const float*)d_in[5];
    const float* dt_proj_w = (const float*)d_in[6];
    const float* dt_proj_b = (const float*)d_in[7];
    const float* A_log     = (const float*)d_in[8];
    const float* D_param   = (const float*)d_in[9];
    const float* out_proj_w= (const float*)d_in[10];
    const float* gate_w    = (const float*)d_in[11];
    const float* gproj_w   = (const float*)d_in[12];
    const float* uproj_w   = (const float*)d_in[13];
    const float* dproj_w   = (const float*)d_in[14];
    const float* rms_a_w   = (const float*)d_in[15];
    const float* rms_f_w   = (const float*)d_in[16];
    const float* head_w1   = (const float*)d_in[17];
    const float* head_w2   = (const float*)d_in[18];
    float* out = (float*)d_out;

    float *h, *hn, *xT, *xr, *xc, *xdbl, *delta, *y, *moe, *w, *cs, *sd, *init;
    cudaGetSymbolAddress((void**)&h,    g_h);
    cudaGetSymbolAddress((void**)&hn,   g_hn);
    cudaGetSymbolAddress((void**)&xT,   g_xT);
    cudaGetSymbolAddress((void**)&xr,   g_xr);
    cudaGetSymbolAddress((void**)&xc,   g_xc);
    cudaGetSymbolAddress((void**)&xdbl, g_xdbl);
    cudaGetSymbolAddress((void**)&delta,g_delta);
    cudaGetSymbolAddress((void**)&y,    g_y);
    cudaGetSymbolAddress((void**)&moe,  g_moe);
    cudaGetSymbolAddress((void**)&w,    g_w);
    cudaGetSymbolAddress((void**)&cs,   g_cs);
    cudaGetSymbolAddress((void**)&sd,   g_sd);
    cudaGetSymbolAddress((void**)&init, g_init);
    float* gu = delta; // reuse

    auto gemm = [&](const float* A, const float* W, float* C, const float* R,
                    const float* rs, int rsStride, int N, int K, int mode) {
        dim3 grid((N + BN - 1) / BN, LL / BM);
        gemm_tc<<<grid, 256>>>(A, W, C, R, rs, rsStride, LL, N, K, mode);
    };

    // h = x.T @ lin_w.T
    transpose_kernel<<<dim3(LL / 32, DIM / 32), dim3(32, 8)>>>(x, xT);
    gemm(xT, lin_w, h, nullptr, nullptr, 0, DIM, DIM, 0);

    for (int i = 0; i < NBLK; i++) {
        // ---- mamba ----
        rmsnorm_kernel<<<LL, DIM>>>(h, rms_a_w, nullptr, hn);
        gemm(hn, in_proj_w + (size_t)i * 2 * DI * DIM, xr, nullptr, nullptr, 0, 2 * DI, DIM, 0);
        conv_kernel<<<(LL * DI + 255) / 256, 256>>>(xr, conv_w + (size_t)i * DI * DCONV,
                                                    conv_b + (size_t)i * DI, xc);
        gemm(xc, x_proj_w + (size_t)i * 48 * DI, xdbl, nullptr, nullptr, 0, 48, DI, 0);
        delta_kernel<<<LL, 256>>>(xdbl, dt_proj_w + (size_t)i * DI * DTR,
                                  dt_proj_b + (size_t)i * DI, delta);
        const float* Alog_i = A_log + (size_t)i * DI * NS;
        scan_p1<<<NCH * (DI / 8), 128>>>(delta, xc, xdbl, Alog_i, cs, sd);
        scan_p2<<<DI * NS / 256, 256>>>(Alog_i, cs, sd, init);
        scan_p3<<<NCH * (DI / 8), 128>>>(delta, xc, xdbl, Alog_i, init,
                                         D_param + (size_t)i * DI, xr, y);
        // h = out_proj(y) + h (residual)
        gemm(y, out_proj_w + (size_t)i * DIM * DI, h, h, nullptr, 0, DIM, DI, 2);

        // ---- MoE ----
        gate_kernel<<<LL / 8, 256>>>(h, gate_w + (size_t)i * NE * DIM, w);
        cudaMemsetAsync(moe, 0, (size_t)LL * DIM * sizeof(float));
        for (int e = 0; e < NE; e++) {
            const float* gp = gproj_w + ((size_t)i * NE + e) * INNER * DIM;
            const float* up = uproj_w + ((size_t)i * NE + e) * INNER * DIM;
            const float* dp = dproj_w + ((size_t)i * NE + e) * DIM * INNER;
            gemm(h, gp, gu, nullptr, nullptr, 0, INNER, DIM, 1);   // gu = silu(h@gp^T)
            gemm(h, up, gu, nullptr, nullptr, 0, INNER, DIM, 3);   // gu *= h@up^T
            gemm(gu, dp, moe, nullptr, w + e, NE, DIM, INNER, 4);  // moe += w[t,e]*(gu@dp^T)
        }
        // h = rmsnorm(moe) + h
        rmsnorm_kernel<<<LL, DIM>>>(moe, rms_f_w, h, h);
    }

    // head
    gemm(h, lin_w, hn, nullptr, nullptr, 0, DIM, DIM, 0);
    gemm(hn, head_w1, xT, nullptr, nullptr, 0, DIM, DIM, 1);
    head2_kernel<<<LL * HOR / 256, 256>>>(xT, head_w2, out);
}

// round 4
// speedup vs baseline: 2.6204x; 1.1432x over previous
#include <cuda_runtime.h>
#include <cuda_bf16.h>
#include <math.h>
#include <stdint.h>

#define LL    8192
#define DIM   256
#define DI    512
#define DCONV 4
#define NS    16
#define DTR   16
#define NE    4
#define INNER 512
#define HOR   32
#define NBLK  8
#define EPSV  1e-3f

#define NCH 128   // scan chunks
#define CL  64    // chunk length (NCH*CL == LL)

// ---------------- scratch (static device allocations only) ----------------
__device__ float g_h   [LL*DIM];
__device__ float g_hn  [LL*DIM];
__device__ float g_xT  [LL*DIM];
__device__ float g_xr  [LL*2*DI];
__device__ float g_xc  [LL*DI];
__device__ float g_xdbl[LL*(DTR+2*NS)];
__device__ float g_delta[LL*DI];
__device__ float g_y   [LL*DI];
__device__ float g_moe [LL*DIM];
__device__ float g_w   [LL*NE];
__device__ float g_cs  [NCH*DI*NS];
__device__ float g_sd  [NCH*DI];
__device__ float g_init[NCH*DI*NS];
__device__ float g_gu  [LL*NE*INNER];   // merged MoE gate/up buffer (L x 2048)

__device__ __forceinline__ float siluf(float x) { return x / (1.f + expf(-x)); }

__device__ __forceinline__ void mma_tf32(float c[4], const unsigned int a[4], const unsigned int b[2]) {
    asm volatile("mma.sync.aligned.m16n8k8.row.col.f32.tf32.tf32.f32 "
        "{%0,%1,%2,%3}, {%4,%5,%6,%7}, {%8,%9}, {%0,%1,%2,%3};"
        : "+f"(c[0]), "+f"(c[1]), "+f"(c[2]), "+f"(c[3])
        : "r"(a[0]), "r"(a[1]), "r"(a[2]), "r"(a[3]), "r"(b[0]), "r"(b[1]));
}

__device__ __forceinline__ void cp_async16(void* dst, const void* src) {
    unsigned int d = (unsigned int)__cvta_generic_to_shared(dst);
    asm volatile("cp.async.cg.shared.global [%0], [%1], 16;\n" :: "r"(d), "l"(src));
}
__device__ __forceinline__ void cp_commit() { asm volatile("cp.async.commit_group;\n"); }
__device__ __forceinline__ void cp_wait0()  { asm volatile("cp.async.wait_group 0;\n"); }
__device__ __forceinline__ void cp_wait1()  { asm volatile("cp.async.wait_group 1;\n"); }

// ---------------- transpose x (DIM,L) -> xT (L,DIM) ----------------
__global__ void transpose_kernel(const float* __restrict__ x, float* __restrict__ xT)
{
    __shared__ float tile[32][33];
    int bx = blockIdx.x * 32;
    int by = blockIdx.y * 32;
    int tx = threadIdx.x, ty = threadIdx.y; // 32 x 8
    #pragma unroll
    for (int i = 0; i < 32; i += 8)
        tile[ty + i][tx] = x[(by + ty + i) * LL + bx + tx];
    __syncthreads();
    #pragma unroll
    for (int i = 0; i < 32; i += 8)
        xT[(bx + ty + i) * DIM + by + tx] = tile[tx][ty + i];
}

// ---------------- tensor-core GEMM: C[M,N] = epi(A[M,K](lda) @ W[N,K]^T) ----------------
// modes: 0 store, 1 silu, 2 add residual R, 3 C *= acc, 4 C += rs[m]*acc, 5 C = rs[m]*acc
// 128x64x32 tiles, cp.async double-buffered smem (raw fp32 bits fed to mma.tf32 = RZ tf32).
#define BM 128
#define BN 64
#define BK 32
#define SST 36
#define GEMM_SMEM ((2*BM*SST + 2*BN*SST)*4)

extern __shared__ unsigned int smem_u[];

__global__ __launch_bounds__(256)
void gemm_tc(const float* __restrict__ A, const float* __restrict__ W,
             float* __restrict__ C, const float* __restrict__ R,
             const float* __restrict__ rs, int rsStride, int lda,
             int M, int N, int K, int mode)
{
    unsigned int* As = smem_u;                 // [2][BM*SST]
    unsigned int* Bs = smem_u + 2 * BM * SST;  // [2][BN*SST]
    int bm = blockIdx.y * BM;
    int bn = blockIdx.x * BN;
    int tid = threadIdx.x;
    int lane = tid & 31;
    int warp = tid >> 5;
    int wm = (warp & 3) * 32;
    int wn = (warp >> 2) * 32;

    float acc[2][4][4];
    #pragma unroll
    for (int mt = 0; mt < 2; mt++)
        #pragma unroll
        for (int nt = 0; nt < 4; nt++)
            #pragma unroll
            for (int q = 0; q < 4; q++) acc[mt][nt][q] = 0.f;

    // issue one K-tile of cp.async into buffer `buf`
    auto issue = [&](int k0, int buf) {
        unsigned int* Ab = As + buf * BM * SST;
        unsigned int* Bb = Bs + buf * BN * SST;
        #pragma unroll
        for (int q = 0; q < 4; q++) {               // A: 1024 granules of 16B
            int g = q * 256 + tid;
            int r = g >> 3, c4 = g & 7;
            cp_async16(Ab + r * SST + c4 * 4,
                       A + (size_t)(bm + r) * lda + k0 + c4 * 4);
        }
        #pragma unroll
        for (int q = 0; q < 2; q++) {               // B: 512 granules
            int g = q * 256 + tid;
            int r = g >> 3, c4 = g & 7;
            int rn = bn + r; if (rn >= N) rn = N - 1;   // clamp (epilogue guards n<N)
            cp_async16(Bb + r * SST + c4 * 4,
                       W + (size_t)rn * K + k0 + c4 * 4);
        }
        cp_commit();
    };

    int nsteps = K / BK;
    issue(0, 0);

    int rq = lane >> 2;
    int cq = lane & 3;
    int buf = 0;

    for (int s = 0; s < nsteps; s++) {
        if (s + 1 < nsteps) { issue((s + 1) * BK, buf ^ 1); cp_wait1(); }
        else cp_wait0();
        __syncthreads();

        const unsigned int* Ab = As + buf * BM * SST;
        const unsigned int* Bb = Bs + buf * BN * SST;
        #pragma unroll
        for (int kk = 0; kk < 4; kk++) {
            int kb = kk * 8 + cq;
            unsigned int a[2][4], b[4][2];
            #pragma unroll
            for (int mt = 0; mt < 2; mt++) {
                int rb = wm + mt * 16 + rq;
                a[mt][0] = Ab[rb * SST + kb];
                a[mt][1] = Ab[(rb + 8) * SST + kb];
                a[mt][2] = Ab[rb * SST + kb + 4];
                a[mt][3] = Ab[(rb + 8) * SST + kb + 4];
            }
            #pragma unroll
            for (int nt = 0; nt < 4; nt++) {
                int cb = wn + nt * 8 + rq;
                b[nt][0] = Bb[cb * SST + kb];
                b[nt][1] = Bb[cb * SST + kb + 4];
            }
            #pragma unroll
            for (int mt = 0; mt < 2; mt++)
                #pragma unroll
                for (int nt = 0; nt < 4; nt++)
                    mma_tf32(acc[mt][nt], a[mt], b[nt]);
        }
        __syncthreads();
        buf ^= 1;
    }

    // epilogue
    int cc = cq * 2;
    #pragma unroll
    for (int mt = 0; mt < 2; mt++) {
        #pragma unroll
        for (int half = 0; half < 2; half++) {
            int m = bm + wm + mt * 16 + rq + half * 8;
            float rsv = (mode >= 4) ? rs[m * rsStride] : 0.f;
            #pragma unroll
            for (int nt = 0; nt < 4; nt++) {
                int n = bn + wn + nt * 8 + cc;
                if (n < N) {
                    size_t o = (size_t)m * N + n;
                    float v0 = acc[mt][nt][half * 2 + 0];
                    float v1 = acc[mt][nt][half * 2 + 1];
                    if (mode == 0) {
                        C[o] = v0; C[o + 1] = v1;
                    } else if (mode == 1) {
                        C[o]     = v0 / (1.f + expf(-v0));
                        C[o + 1] = v1 / (1.f + expf(-v1));
                    } else if (mode == 2) {
                        C[o] = v0 + R[o]; C[o + 1] = v1 + R[o + 1];
                    } else if (mode == 3) {
                        C[o] *= v0; C[o + 1] *= v1;
                    } else if (mode == 4) {
                        C[o] += rsv * v0; C[o + 1] += rsv * v1;
                    } else {
                        C[o] = rsv * v0; C[o + 1] = rsv * v1;
                    }
                }
            }
        }
    }
}

// ---------------- rmsnorm over rows of 256 (optional residual add) ----------------
__global__ void rmsnorm_kernel(const float* __restrict__ in, const float* __restrict__ w,
                               const float* __restrict__ addres, float* __restrict__ out)
{
    int l = blockIdx.x;
    int t = threadIdx.x; // 256
    float v = in[l * DIM + t];
    __shared__ float red[8];
    float s = v * v;
    #pragma unroll
    for (int o = 16; o > 0; o >>= 1) s += __shfl_xor_sync(0xffffffffu, s, o);
    if ((t & 31) == 0) red[t >> 5] = s;
    __syncthreads();
    if (t < 8) {
        float x2 = red[t];
        #pragma unroll
        for (int o = 4; o > 0; o >>= 1) x2 += __shfl_xor_sync(0xffu, x2, o);
        if (t == 0) red[0] = x2;
    }
    __syncthreads();
    float rms = rsqrtf(red[0] / (float)DIM + EPSV);
    float r = w[t] * v * rms;
    if (addres) r += addres[l * DIM + t];
    out[l * DIM + t] = r;
}

// ---------------- causal depthwise conv(4) + bias + silu ----------------
__global__ void conv_kernel(const float* __restrict__ xr, const float* __restrict__ cw,
                            const float* __restrict__ cb, float* __restrict__ xc)
{
    int idx = blockIdx.x * blockDim.x + threadIdx.x;
    if (idx >= LL * DI) return;
    int c = idx % DI, l = idx / DI;
    float w0 = cw[c * 4 + 0], w1 = cw[c * 4 + 1], w2 = cw[c * 4 + 2], w3 = cw[c * 4 + 3];
    float acc = cb[c];
    if (l >= 3) acc += xr[(size_t)(l - 3) * (2 * DI) + c] * w0;
    if (l >= 2) acc += xr[(size_t)(l - 2) * (2 * DI) + c] * w1;
    if (l >= 1) acc += xr[(size_t)(l - 1) * (2 * DI) + c] * w2;
    acc += xr[(size_t)l * (2 * DI) + c] * w3;
    xc[idx] = siluf(acc);
}

// ---------------- delta = softplus(dr @ dtw^T + dtb) ----------------
__global__ void delta_kernel(const float* __restrict__ xdbl, const float* __restrict__ dtw,
                             const float* __restrict__ dtb, float* __restrict__ delta)
{
    int l = blockIdx.x;
    __shared__ float dr[DTR];
    if (threadIdx.x < DTR) dr[threadIdx.x] = xdbl[l * 48 + threadIdx.x];
    __syncthreads();
    for (int d = threadIdx.x; d < DI; d += blockDim.x) {
        float acc = dtb[d];
        #pragma unroll
        for (int r = 0; r < DTR; r++) acc += dr[r] * dtw[d * DTR + r];
        float sp = (acc > 20.f) ? acc : log1pf(expf(acc));
        delta[(size_t)l * DI + d] = sp;
    }
}

// ---------------- gate: scores, top-2 softmax weights ----------------
__global__ void gate_kernel(const float* __restrict__ h, const float* __restrict__ gw,
                            float* __restrict__ wout)
{
    __shared__ float sgw[NE * DIM];
    int tid = threadIdx.x; // 256
    for (int i = tid; i < NE * DIM; i += 256) sgw[i] = gw[i];
    __syncthreads();
    int warp = tid >> 5, lane = tid & 31;
    int t = blockIdx.x * 8 + warp;
    float acc[NE] = {0.f, 0.f, 0.f, 0.f};
    for (int k = lane; k < DIM; k += 32) {
        float hv = h[(size_t)t * DIM + k];
        #pragma unroll
        for (int e = 0; e < NE; e++) acc[e] += hv * sgw[e * DIM + k];
    }
    #pragma unroll
    for (int e = 0; e < NE; e++)
        #pragma unroll
        for (int o = 16; o > 0; o >>= 1) acc[e] += __shfl_xor_sync(0xffffffffu, acc[e], o);
    if (lane == 0) {
        int i1 = 0; float v1 = acc[0];
        for (int e = 1; e < NE; e++) if (acc[e] > v1) { v1 = acc[e]; i1 = e; }
        int i2 = -1; float v2 = -1e30f;
        for (int e = 0; e < NE; e++) if (e != i1 && acc[e] > v2) { v2 = acc[e]; i2 = e; }
        float ew = expf(v2 - v1);
        float w1 = 1.f / (1.f + ew), w2 = ew / (1.f + ew);
        float w[NE] = {0.f, 0.f, 0.f, 0.f};
        w[i1] = w1; w[i2] = w2;
        #pragma unroll
        for (int e = 0; e < NE; e++) wout[t * NE + e] = w[e];
    }
}

// ---------------- chunked selective scan ----------------
__global__ void scan_p1(const float* __restrict__ delta, const float* __restrict__ xc,
                        const float* __restrict__ xdbl, const float* __restrict__ Alog,
                        float* __restrict__ cs, float* __restrict__ sd)
{
    int b = blockIdx.x;          // NCH * (DI/8)
    int chunk = b >> 6;
    int dg = b & 63;
    int tid = threadIdx.x;       // 128 = 8 d x 16 n
    int dl = tid >> 4, n = tid & 15;
    int d = dg * 8 + dl;
    float Acoef = -__expf(Alog[d * NS + n]);
    float s = 0.f, sdl = 0.f;
    int l0 = chunk * CL;
    for (int i = 0; i < CL; i++) {
        int l = l0 + i;
        float dt = delta[(size_t)l * DI + d];
        float x  = xc[(size_t)l * DI + d];
        float Bv = xdbl[l * 48 + DTR + n];
        s = __expf(dt * Acoef) * s + dt * Bv * x;
        sdl += dt;
    }
    cs[((size_t)chunk * DI + d) * NS + n] = s;
    if (n == 0) sd[chunk * DI + d] = sdl;
}

__global__ void scan_p2(const float* __restrict__ Alog, const float* __restrict__ cs,
                        const float* __restrict__ sd, float* __restrict__ init)
{
    int idx = blockIdx.x * blockDim.x + threadIdx.x; // DI*NS = 8192
    int d = idx >> 4, n = idx & 15;
    float Acoef = -__expf(Alog[d * NS + n]);
    float S = 0.f;
    for (int c = 0; c < NCH; c++) {
        init[((size_t)c * DI + d) * NS + n] = S;
        S = __expf(Acoef * sd[c * DI + d]) * S + cs[((size_t)c * DI + d) * NS + n];
    }
}

__global__ void scan_p3(const float* __restrict__ delta, const float* __restrict__ xc,
                        const float* __restrict__ xdbl, const float* __restrict__ Alog,
                        const float* __restrict__ init, const float* __restrict__ Dp,
                        const float* __restrict__ xr, float* __restrict__ y)
{
    int b = blockIdx.x;
    int chunk = b >> 6;
    int dg = b & 63;
    int tid = threadIdx.x;
    int dl = tid >> 4, n = tid & 15;
    int d = dg * 8 + dl;
    float Acoef = -__expf(Alog[d * NS + n]);
    float s = init[((size_t)chunk * DI + d) * NS + n];
    float Dv = Dp[d];
    int l0 = chunk * CL;
    for (int i = 0; i < CL; i++) {
        int l = l0 + i;
        float dt = delta[(size_t)l * DI + d];
        float x  = xc[(size_t)l * DI + d];
        float Bv = xdbl[l * 48 + DTR + n];
        float Cv = xdbl[l * 48 + DTR + NS + n];
        s = __expf(dt * Acoef) * s + dt * Bv * x;
        float part = s * Cv;
        #pragma unroll
        for (int o = 1; o < 16; o <<= 1)
            part += __shfl_xor_sync(0xffffffffu, part, o, 16);
        if (n == 0) {
            float res = xr[(size_t)l * (2 * DI) + DI + d];
            y[(size_t)l * DI + d] = (part + x * Dv) * siluf(res);
        }
    }
}

// ---------------- head2: out[o,l] = sigmoid(a[l,:] . w2[o,:]) ----------------
__global__ void head2_kernel(const float* __restrict__ a, const float* __restrict__ w2,
                             float* __restrict__ out)
{
    int idx = blockIdx.x * blockDim.x + threadIdx.x; // LL*HOR
    int o = idx & 31, l = idx >> 5;
    const float* ar = a + (size_t)l * DIM;
    const float* wr = w2 + (size_t)o * DIM;
    float acc = 0.f;
    #pragma unroll 8
    for (int k = 0; k < DIM; k++) acc += ar[k] * wr[k];
    out[(size_t)o * LL + l] = 1.f / (1.f + expf(-acc));
}

// ---------------- host orchestration ----------------
extern "C" void kernel_launch(void* const* d_in, const int* in_sizes, int n_in,
                              void* d_out, int out_size)
{
    const float* x         = (const float*)d_in[0];
    const float* lin_w     = (const float*)d_in[1];
    const float* in_proj_w = (const float*)d_in[2];
    const float* conv_w    = (const float*)d_in[3];
    const float* conv_b    = (const float*)d_in[4];
    const float* x_proj_w  = (const float*)d_in[5];
    const float* dt_proj_w = (const float*)d_in[6];
    const float* dt_proj_b = (const float*)d_in[7];
    const float* A_log     = (const float*)d_in[8];
    const float* D_param   = (const float*)d_in[9];
    const float* out_proj_w= (const float*)d_in[10];
    const float* gate_w    = (const float*)d_in[11];
    const float* gproj_w   = (const float*)d_in[12];
    const float* uproj_w   = (const float*)d_in[13];
    const float* dproj_w   = (const float*)d_in[14];
    const float* rms_a_w   = (const float*)d_in[15];
    const float* rms_f_w   = (const float*)d_in[16];
    const float* head_w1   = (const float*)d_in[17];
    const float* head_w2   = (const float*)d_in[18];
    float* out = (float*)d_out;

    float *h, *hn, *xT, *xr, *xc, *xdbl, *delta, *y, *moe, *w, *cs, *sd, *init, *gu;
    cudaGetSymbolAddress((void**)&h,    g_h);
    cudaGetSymbolAddress((void**)&hn,   g_hn);
    cudaGetSymbolAddress((void**)&xT,   g_xT);
    cudaGetSymbolAddress((void**)&xr,   g_xr);
    cudaGetSymbolAddress((void**)&xc,   g_xc);
    cudaGetSymbolAddress((void**)&xdbl, g_xdbl);
    cudaGetSymbolAddress((void**)&delta,g_delta);
    cudaGetSymbolAddress((void**)&y,    g_y);
    cudaGetSymbolAddress((void**)&moe,  g_moe);
    cudaGetSymbolAddress((void**)&w,    g_w);
    cudaGetSymbolAddress((void**)&cs,   g_cs);
    cudaGetSymbolAddress((void**)&sd,   g_sd);
    cudaGetSymbolAddress((void**)&init, g_init);
    cudaGetSymbolAddress((void**)&gu,   g_gu);

    static bool attr_set = false;
    if (!attr_set) {
        cudaFuncSetAttribute(gemm_tc, cudaFuncAttributeMaxDynamicSharedMemorySize, GEMM_SMEM);
        attr_set = true;
    }

    auto gemm = [&](const float* A, const float* W, float* C, const float* R,
                    const float* rs, int rsStride, int lda, int N, int K, int mode) {
        dim3 grid((N + BN - 1) / BN, LL / BM);
        gemm_tc<<<grid, 256, GEMM_SMEM>>>(A, W, C, R, rs, rsStride, lda, LL, N, K, mode);
    };

    // h = x.T @ lin_w.T
    transpose_kernel<<<dim3(LL / 32, DIM / 32), dim3(32, 8)>>>(x, xT);
    gemm(xT, lin_w, h, nullptr, nullptr, 0, DIM, DIM, DIM, 0);

    for (int i = 0; i < NBLK; i++) {
        // ---- mamba ----
        rmsnorm_kernel<<<LL, DIM>>>(h, rms_a_w, nullptr, hn);
        gemm(hn, in_proj_w + (size_t)i * 2 * DI * DIM, xr, nullptr, nullptr, 0, DIM, 2 * DI, DIM, 0);
        conv_kernel<<<(LL * DI + 255) / 256, 256>>>(xr, conv_w + (size_t)i * DI * DCONV,
                                                    conv_b + (size_t)i * DI, xc);
        gemm(xc, x_proj_w + (size_t)i * 48 * DI, xdbl, nullptr, nullptr, 0, DI, 48, DI, 0);
        delta_kernel<<<LL, 256>>>(xdbl, dt_proj_w + (size_t)i * DI * DTR,
                                  dt_proj_b + (size_t)i * DI, delta);
        const float* Alog_i = A_log + (size_t)i * DI * NS;
        scan_p1<<<NCH * (DI / 8), 128>>>(delta, xc, xdbl, Alog_i, cs, sd);
        scan_p2<<<DI * NS / 256, 256>>>(Alog_i, cs, sd, init);
        scan_p3<<<NCH * (DI / 8), 128>>>(delta, xc, xdbl, Alog_i, init,
                                         D_param + (size_t)i * DI, xr, y);
        // h = out_proj(y) + h (residual)
        gemm(y, out_proj_w + (size_t)i * DIM * DI, h, h, nullptr, 0, DI, DIM, DI, 2);

        // ---- MoE (merged over experts) ----
        gate_kernel<<<LL / 8, 256>>>(h, gate_w + (size_t)i * NE * DIM, w);
        // gu = silu(h @ Gall^T)  (N = NE*INNER = 2048)
        gemm(h, gproj_w + (size_t)i * NE * INNER * DIM, gu, nullptr, nullptr, 0,
             DIM, NE * INNER, DIM, 1);
        // gu *= h @ Uall^T
        gemm(h, uproj_w + (size_t)i * NE * INNER * DIM, gu, nullptr, nullptr, 0,
             DIM, NE * INNER, DIM, 3);
        // moe = sum_e w[t,e] * (gu_e @ dp_e^T)
        for (int e = 0; e < NE; e++) {
            const float* dp = dproj_w + ((size_t)i * NE + e) * DIM * INNER;
            gemm(gu + (size_t)e * INNER, dp, moe, nullptr, w + e, NE,
                 NE * INNER, DIM, INNER, e == 0 ? 5 : 4);
        }
        // h = rmsnorm(moe) + h
        rmsnorm_kernel<<<LL, DIM>>>(moe, rms_f_w, h, h);
    }

    // head
    gemm(h, lin_w, hn, nullptr, nullptr, 0, DIM, DIM, DIM, 0);
    gemm(hn, head_w1, xT, nullptr, nullptr, 0, DIM, DIM, DIM, 1);
    head2_kernel<<<LL * HOR / 256, 256>>>(xT, head_w2, out);
}